// round 5
// baseline (speedup 1.0000x reference)
#include <cuda_runtime.h>
#include <cuda_bf16.h>
#include <cstdint>

// SigLipLoss: loss = (1/N) * sum_ij softplus(s_ij), sign-flip on diagonal.
// Round 4: persistent CTAs, 256x128 tiles, bf16 mma.sync,
// mbarrier-based producer/consumer pipeline (no per-chunk __syncthreads),
// finalize folded into the persistent kernel.

#define NN 8192
#define DD 768
#define BM 256
#define BN 128
#define BK 32
#define NTILES (NN / BM * NN / BN)    // 2048
#define KITERS (DD / BK)              // 24
#define NCTA 148
#define ROWBYTES (DD * 2)             // 1536

#define A_B   (BM * 64)               // 16384
#define STAGE_B ((BM + BN) * 64)      // 24576
#define STAGES 4
#define CTRL_B 256
#define SMEM_TOTAL (STAGES * STAGE_B + CTRL_B + 128)

__device__ __align__(16) __nv_bfloat16 g_Abf[NN * DD];
__device__ __align__(16) __nv_bfloat16 g_Bbf[NN * DD];
__device__ float g_partials[NTILES];
__device__ unsigned g_done;

__device__ __forceinline__ uint32_t smem_u32(const void* p) {
    uint32_t r;
    asm("{ .reg .u64 t; cvta.to.shared.u64 t, %1; cvt.u32.u64 %0, t; }"
        : "=r"(r) : "l"(p));
    return r;
}
__device__ __forceinline__ void cpa16(uint32_t dst, const void* src) {
    asm volatile("cp.async.cg.shared.global [%0], [%1], 16;"
                 :: "r"(dst), "l"(__cvta_generic_to_global(src)) : "memory");
}
__device__ __forceinline__ void mbar_init(uint32_t a, uint32_t cnt) {
    asm volatile("mbarrier.init.shared.b64 [%0], %1;" :: "r"(a), "r"(cnt) : "memory");
}
__device__ __forceinline__ void mbar_arrive(uint32_t a) {
    asm volatile("mbarrier.arrive.shared.b64 _, [%0];" :: "r"(a) : "memory");
}
__device__ __forceinline__ void cpasync_arrive(uint32_t a) {
    asm volatile("cp.async.mbarrier.arrive.noinc.shared.b64 [%0];"
                 :: "r"(a) : "memory");
}
__device__ __forceinline__ void mbar_wait(uint32_t a, uint32_t parity) {
    asm volatile(
        "{\n\t.reg .pred P;\n"
        "W_%=:\n\t"
        "mbarrier.try_wait.parity.acquire.cta.shared::cta.b64 P, [%0], %1, 0x989680;\n\t"
        "@P bra.uni D_%=;\n\t"
        "bra.uni W_%=;\n"
        "D_%=:\n\t}"
        :: "r"(a), "r"(parity) : "memory");
}
__device__ __forceinline__ void ldm_x4(uint32_t* r, uint32_t addr) {
    asm volatile("ldmatrix.sync.aligned.m8n8.x4.shared.b16 {%0,%1,%2,%3}, [%4];"
                 : "=r"(r[0]), "=r"(r[1]), "=r"(r[2]), "=r"(r[3]) : "r"(addr));
}
__device__ __forceinline__ void mma16816(float* c, const uint32_t* a,
                                         const uint32_t* b) {
    asm volatile(
        "mma.sync.aligned.m16n8k16.row.col.f32.bf16.bf16.f32 "
        "{%0,%1,%2,%3}, {%4,%5,%6,%7}, {%8,%9}, {%0,%1,%2,%3};"
        : "+f"(c[0]), "+f"(c[1]), "+f"(c[2]), "+f"(c[3])
        : "r"(a[0]), "r"(a[1]), "r"(a[2]), "r"(a[3]), "r"(b[0]), "r"(b[1]));
}

__global__ void convert_kernel(const float* __restrict__ A,
                               const float* __restrict__ B) {
    if (blockIdx.x == 0 && threadIdx.x == 0) g_done = 0;
    const int total4 = NN * DD / 4;
    const int stride = gridDim.x * blockDim.x;
    __nv_bfloat162* pa = (__nv_bfloat162*)g_Abf;
    __nv_bfloat162* pb = (__nv_bfloat162*)g_Bbf;
    for (int i = blockIdx.x * blockDim.x + threadIdx.x; i < total4; i += stride) {
        float4 a = ((const float4*)A)[i];
        float4 b = ((const float4*)B)[i];
        pa[2 * i + 0] = __floats2bfloat162_rn(a.x, a.y);
        pa[2 * i + 1] = __floats2bfloat162_rn(a.z, a.w);
        pb[2 * i + 0] = __floats2bfloat162_rn(b.x, b.y);
        pb[2 * i + 1] = __floats2bfloat162_rn(b.z, b.w);
    }
}

__global__ __launch_bounds__(512, 1) void siglip_mma_kernel(float* __restrict__ out) {
    extern __shared__ char smem_raw[];
    __shared__ unsigned s_last;
    uint32_t sbase = smem_u32(smem_raw);
    sbase = (sbase + 127u) & ~127u;
    const uint32_t ctrl = sbase + STAGES * STAGE_B;   // mbarriers + red
    // ctrl+0..31: full[4], ctrl+32..63: empty[4], ctrl+64..: red[16]

    const int tid  = threadIdx.x;
    const int wid  = tid >> 5;
    const int lane = tid & 31;
    const int warp_m = wid & 7;
    const int warp_n = wid >> 3;
    const int cta = blockIdx.x;

    if (tid == 0) {
#pragma unroll
        for (int s = 0; s < 4; ++s) {
            mbar_init(ctrl + s * 8, 512);        // full
            mbar_init(ctrl + 32 + s * 8, 16);    // empty
        }
    }
    __syncthreads();

    const int ntiles = (NTILES - cta + NCTA - 1) / NCTA;
    const int C = ntiles * KITERS;

    // ---- producer mapping ----
    const int r0 = tid >> 2;
    const int c4 = tid & 3;
    const uint32_t swz = (uint32_t)((c4 ^ ((r0 >> 1) & 3)) * 16);
    const uint32_t dstA0 = r0 * 64 + swz;
    const uint32_t dstA1 = dstA0 + 128 * 64;
    const uint32_t dstB0 = A_B + r0 * 64 + swz;
    const uint32_t cB16 = c4 * 16;

    int pKB = 0, pG = cta;
    const char* bA0 = (const char*)g_Abf
        + ((size_t)(pG >> 6) * BM + r0) * ROWBYTES + cB16;
    const char* bA1 = bA0 + (size_t)128 * ROWBYTES;
    const char* bB0 = (const char*)g_Bbf
        + ((size_t)(pG & 63) * BN + r0) * ROWBYTES + cB16;

#define ISSUE(stage) do {                                                \
        const uint32_t stb = sbase + (uint32_t)(stage) * STAGE_B;        \
        cpa16(stb + dstA0, bA0 + pKB);                                   \
        cpa16(stb + dstA1, bA1 + pKB);                                   \
        cpa16(stb + dstB0, bB0 + pKB);                                   \
        cpasync_arrive(ctrl + (uint32_t)(stage) * 8);                    \
        pKB += 64;                                                       \
        if (pKB == DD * 2) {                                             \
            pKB = 0; pG += NCTA;                                         \
            if (pG < NTILES) {                                           \
                bA0 = (const char*)g_Abf                                 \
                    + ((size_t)(pG >> 6) * BM + r0) * ROWBYTES + cB16;   \
                bA1 = bA0 + (size_t)128 * ROWBYTES;                      \
                bB0 = (const char*)g_Bbf                                 \
                    + ((size_t)(pG & 63) * BN + r0) * ROWBYTES + cB16;   \
            }                                                            \
        }                                                                \
    } while (0)

    // ---- ldmatrix per-lane addresses (XOR swizzle, as R3) ----
    const int rowA = warp_m * 32 + (lane & 15);
    const uint32_t xa = (uint32_t)(((lane & 15) >> 1) & 3);
    const uint32_t ca = (uint32_t)(lane >> 4);
    const uint32_t aBase = rowA * 64;
    const uint32_t swzA0 = ((0 + ca) ^ xa) * 16;
    const uint32_t swzA1 = ((2 + ca) ^ xa) * 16;

    const int rowB = warp_n * 64 + (lane & 7) + ((lane >> 4) & 1) * 8;
    const uint32_t xb = (uint32_t)((rowB >> 1) & 3);
    const uint32_t cb = (uint32_t)((lane >> 3) & 1);
    const uint32_t bBase = A_B + rowB * 64;
    const uint32_t swzB0 = ((0 + cb) ^ xb) * 16;
    const uint32_t swzB1 = ((2 + cb) ^ xb) * 16;

    float* red = (float*)(smem_raw + (ctrl - smem_u32(smem_raw)) + 64);

    int issued = 0;
#pragma unroll
    for (int i = 0; i < 3; ++i) { ISSUE(issued & 3); ++issued; }

    int ch = 0;
    int g = cta;
#pragma unroll 1
    for (int t = 0; t < ntiles; ++t, g += NCTA) {
        float acc[2][8][4];
#pragma unroll
        for (int mt = 0; mt < 2; ++mt)
#pragma unroll
            for (int nt = 0; nt < 8; ++nt)
#pragma unroll
                for (int v = 0; v < 4; ++v) acc[mt][nt][v] = 0.0f;

#pragma unroll 1
        for (int it = 0; it < KITERS; ++it, ++ch) {
            // ---- produce chunk (ch+3) into stage (issued&3) ----
            if (issued < C) {
                const int s = issued & 3;
                if (issued >= 4) {
                    if (lane == 0)
                        mbar_wait(ctrl + 32 + s * 8, ((issued >> 2) + 1) & 1);
                    __syncwarp();
                }
                ISSUE(s);
                ++issued;
            }
            // ---- consume chunk ch ----
            const int s = ch & 3;
            if (lane == 0) mbar_wait(ctrl + s * 8, (ch >> 2) & 1);
            __syncwarp();

            const uint32_t sS = sbase + (uint32_t)s * STAGE_B;
            uint32_t a[2][2][4], b[2][4][4];
#pragma unroll
            for (int kk = 0; kk < 2; ++kk) {
                const uint32_t sa = kk ? swzA1 : swzA0;
                const uint32_t sb = kk ? swzB1 : swzB0;
#pragma unroll
                for (int mt = 0; mt < 2; ++mt)
                    ldm_x4(a[kk][mt], sS + aBase + mt * 1024 + sa);
#pragma unroll
                for (int np = 0; np < 4; ++np)
                    ldm_x4(b[kk][np], sS + bBase + np * 1024 + sb);
            }
            __syncwarp();
            if (lane == 0) mbar_arrive(ctrl + 32 + s * 8);   // stage consumed

#pragma unroll
            for (int kk = 0; kk < 2; ++kk)
#pragma unroll
                for (int mt = 0; mt < 2; ++mt)
#pragma unroll
                    for (int nt = 0; nt < 8; ++nt)
                        mma16816(acc[mt][nt], a[kk][mt],
                                 &b[kk][nt >> 1][(nt & 1) * 2]);
        }

        // ---- tile epilogue ----
        const float SCALE = 2.302585092994046f, BIAS = -10.0f;
        const int rowBase = (g >> 6) * BM;
        const int colBase = (g & 63) * BN;
        float lsum = 0.0f;
#pragma unroll
        for (int mt = 0; mt < 2; ++mt) {
            const int row0 = rowBase + warp_m * 32 + mt * 16 + (lane >> 2);
#pragma unroll
            for (int nt = 0; nt < 8; ++nt) {
                const int col0 = colBase + warp_n * 64 + nt * 8 + (lane & 3) * 2;
#pragma unroll
                for (int v = 0; v < 4; ++v) {
                    const int row = row0 + (v >> 1) * 8;
                    const int col = col0 + (v & 1);
                    float z = fmaf(acc[mt][nt][v], SCALE, BIAS);
                    if (row == col) z = -z;
                    lsum += fmaxf(z, 0.0f) + __logf(1.0f + __expf(-fabsf(z)));
                }
            }
        }
#pragma unroll
        for (int off = 16; off > 0; off >>= 1)
            lsum += __shfl_down_sync(0xFFFFFFFFu, lsum, off);
        if (lane == 0) red[wid] = lsum;
        __syncthreads();
        if (tid == 0) {
            float s = 0.0f;
#pragma unroll
            for (int i = 0; i < 16; ++i) s += red[i];
            g_partials[g] = s;
        }
        __syncthreads();
    }
#undef ISSUE

    // ---- last CTA finalizes (deterministic fixed-order sum) ----
    __threadfence();
    __syncthreads();
    if (tid == 0)
        s_last = (atomicAdd(&g_done, 1u) == NCTA - 1) ? 1u : 0u;
    __syncthreads();
    if (s_last) {
        __threadfence();
        double* sd = (double*)smem_raw;    // stage buffers dead now
        double s = 0.0;
        for (int i = tid; i < NTILES; i += 512)
            s += (double)g_partials[i];
        sd[tid] = s;
        __syncthreads();
#pragma unroll
        for (int off = 256; off > 0; off >>= 1) {
            if (tid < off) sd[tid] += sd[tid + off];
            __syncthreads();
        }
        if (tid == 0) out[0] = (float)(sd[0] / (double)NN);
    }
}

extern "C" void kernel_launch(void* const* d_in, const int* in_sizes, int n_in,
                              void* d_out, int out_size) {
    cudaFuncSetAttribute(siglip_mma_kernel,
                         cudaFuncAttributeMaxDynamicSharedMemorySize, SMEM_TOTAL);
    convert_kernel<<<2048, 256>>>((const float*)d_in[0], (const float*)d_in[1]);
    siglip_mma_kernel<<<NCTA, 512, SMEM_TOTAL>>>((float*)d_out);
}